// round 3
// baseline (speedup 1.0000x reference)
#include <cuda_runtime.h>
#include <math.h>
#include <stdint.h>

#define REF_Y 0.5f
#define EPSF  1e-08f

#define NBLK 8      // one cluster of 8 CTAs (portable max)
#define NTHR 256    // 8 warps per CTA; 2048 threads total -> 1 float4/thread

__device__ __forceinline__ uint32_t smem_u32(const void* p) {
    uint32_t a;
    asm("{ .reg .u64 t; cvta.to.shared.u64 t, %1; cvt.u32.u64 %0, t; }"
        : "=r"(a) : "l"(p));
    return a;
}

__global__ __launch_bounds__(NTHR, 1) __cluster_dims__(NBLK, 1, 1)
void lamse_kernel(const float* __restrict__ x,
                  const float* __restrict__ t,
                  float* __restrict__ out,
                  int n) {
    // cross-CTA partial landing zone (lives in CTA 0's SMEM; same static
    // offset in every CTA, addressed via mapa)
    __shared__ float part[NBLK][8];
    __shared__ float sh[NTHR / 32][8];

    const int tid = threadIdx.x;
    const int wid = tid >> 5;
    const int lid = tid & 31;
    uint32_t rank;
    asm("mov.u32 %0, %%cluster_ctarank;" : "=r"(rank));

    float s0 = 0.f;  // Σ valid·e²·w
    float s1 = 0.f;  // Σ valid·w
    float s2 = 0.f;  // Σ w
    float s3 = 0.f;  // Σ e
    float s4 = 0.f;  // Σ e·w
    float s5 = 0.f;  // Σ e²
    float s6 = 0.f;  // Σ e²·w

    const int n4 = n >> 2;
    const float4* __restrict__ x4 = (const float4*)x;
    const float4* __restrict__ t4 = (const float4*)t;
    const int gt = (int)rank * NTHR + tid;

    for (int i = gt; i < n4; i += NBLK * NTHR) {
        float4 xv = x4[i];
        float4 tv = t4[i];
        #pragma unroll
        for (int k = 0; k < 4; ++k) {
            float xj = (k == 0) ? xv.x : (k == 1) ? xv.y : (k == 2) ? xv.z : xv.w;
            float tj = (k == 0) ? tv.x : (k == 1) ? tv.y : (k == 2) ? tv.z : tv.w;

            float w = fabsf(REF_Y - tj) / (fabsf(REF_Y) + fabsf(tj) + EPSF);
            w = fminf(fmaxf(w, 0.1f), 2.0f);

            bool valid = !isnan(tj);
            float tsafe = valid ? tj : 0.0f;
            float dv = tsafe - xj;
            s0 += valid ? dv * dv * w : 0.0f;
            s1 += valid ? w : 0.0f;

            float e = xj - tj;
            s2 += w;
            s3 += e;
            s4 += e * w;
            float e2 = e * e;
            s5 += e2;
            s6 += e2 * w;
        }
    }
    // generic scalar tail
    for (int i = (n4 << 2) + gt; i < n; i += NBLK * NTHR) {
        float xj = x[i], tj = t[i];
        float w = fabsf(REF_Y - tj) / (fabsf(REF_Y) + fabsf(tj) + EPSF);
        w = fminf(fmaxf(w, 0.1f), 2.0f);
        bool valid = !isnan(tj);
        float tsafe = valid ? tj : 0.0f;
        float dv = tsafe - xj;
        s0 += valid ? dv * dv * w : 0.0f;
        s1 += valid ? w : 0.0f;
        float e = xj - tj;
        s2 += w; s3 += e; s4 += e * w; s5 += e * e; s6 += e * e * w;
    }

    // warp shuffle reduce
    #pragma unroll
    for (int off = 16; off > 0; off >>= 1) {
        s0 += __shfl_down_sync(0xffffffffu, s0, off);
        s1 += __shfl_down_sync(0xffffffffu, s1, off);
        s2 += __shfl_down_sync(0xffffffffu, s2, off);
        s3 += __shfl_down_sync(0xffffffffu, s3, off);
        s4 += __shfl_down_sync(0xffffffffu, s4, off);
        s5 += __shfl_down_sync(0xffffffffu, s5, off);
        s6 += __shfl_down_sync(0xffffffffu, s6, off);
    }

    if (lid == 0) {
        sh[wid][0] = s0; sh[wid][1] = s1; sh[wid][2] = s2; sh[wid][3] = s3;
        sh[wid][4] = s4; sh[wid][5] = s5; sh[wid][6] = s6;
    }
    __syncthreads();

    if (wid == 0) {
        const int nw = NTHR / 32;   // 8
        float v0 = (lid < nw) ? sh[lid][0] : 0.f;
        float v1 = (lid < nw) ? sh[lid][1] : 0.f;
        float v2 = (lid < nw) ? sh[lid][2] : 0.f;
        float v3 = (lid < nw) ? sh[lid][3] : 0.f;
        float v4 = (lid < nw) ? sh[lid][4] : 0.f;
        float v5 = (lid < nw) ? sh[lid][5] : 0.f;
        float v6 = (lid < nw) ? sh[lid][6] : 0.f;
        #pragma unroll
        for (int off = 4; off > 0; off >>= 1) {
            v0 += __shfl_down_sync(0xffffffffu, v0, off);
            v1 += __shfl_down_sync(0xffffffffu, v1, off);
            v2 += __shfl_down_sync(0xffffffffu, v2, off);
            v3 += __shfl_down_sync(0xffffffffu, v3, off);
            v4 += __shfl_down_sync(0xffffffffu, v4, off);
            v5 += __shfl_down_sync(0xffffffffu, v5, off);
            v6 += __shfl_down_sync(0xffffffffu, v6, off);
        }
        if (lid == 0) {
            // write this CTA's 7 partials into CTA 0's SMEM via DSMEM
            uint32_t local = smem_u32(&part[rank][0]);
            uint32_t remote;
            asm("mapa.shared::cluster.u32 %0, %1, %2;"
                : "=r"(remote) : "r"(local), "r"(0));
            asm volatile("st.shared::cluster.f32 [%0+0],  %1;" :: "r"(remote), "f"(v0) : "memory");
            asm volatile("st.shared::cluster.f32 [%0+4],  %1;" :: "r"(remote), "f"(v1) : "memory");
            asm volatile("st.shared::cluster.f32 [%0+8],  %1;" :: "r"(remote), "f"(v2) : "memory");
            asm volatile("st.shared::cluster.f32 [%0+12], %1;" :: "r"(remote), "f"(v3) : "memory");
            asm volatile("st.shared::cluster.f32 [%0+16], %1;" :: "r"(remote), "f"(v4) : "memory");
            asm volatile("st.shared::cluster.f32 [%0+20], %1;" :: "r"(remote), "f"(v5) : "memory");
            asm volatile("st.shared::cluster.f32 [%0+24], %1;" :: "r"(remote), "f"(v6) : "memory");
        }
    }

    // cluster barrier: arrive=release (orders DSMEM stores), wait=acquire
    asm volatile("barrier.cluster.arrive.aligned;" ::: "memory");
    asm volatile("barrier.cluster.wait.aligned;"   ::: "memory");

    if (rank == 0 && wid == 0) {
        float v0 = 0.f, v1 = 0.f, v2 = 0.f, v3 = 0.f, v4 = 0.f, v5 = 0.f, v6 = 0.f;
        if (lid < NBLK) {
            v0 = part[lid][0]; v1 = part[lid][1]; v2 = part[lid][2];
            v3 = part[lid][3]; v4 = part[lid][4]; v5 = part[lid][5];
            v6 = part[lid][6];
        }
        #pragma unroll
        for (int off = NBLK / 2; off > 0; off >>= 1) {
            v0 += __shfl_down_sync(0xffffffffu, v0, off);
            v1 += __shfl_down_sync(0xffffffffu, v1, off);
            v2 += __shfl_down_sync(0xffffffffu, v2, off);
            v3 += __shfl_down_sync(0xffffffffu, v3, off);
            v4 += __shfl_down_sync(0xffffffffu, v4, off);
            v5 += __shfl_down_sync(0xffffffffu, v5, off);
            v6 += __shfl_down_sync(0xffffffffu, v6, off);
        }
        if (lid == 0) {
            float fn = (float)n;
            float mse = v0 / v1;   // Σvalid·e²w / Σvalid·w

            // pairwise term collapses:
            // num = 0.5*(n·Σe²w − 2·Σe·Σew + Σw·Σe²), den = 0.5*(n−1)·Σw
            float num = 0.5f * (fn * v6 - 2.0f * v3 * v4 + v2 * v5);
            float den = 0.5f * (fn - 1.0f) * v2;
            float c = num / den;

            // do_scale branch: c·(mse/c) == mse
            bool do_scale = (c > EPSF) && (mse > EPSF) && (c < mse);
            float cs = do_scale ? mse : c;

            out[0] = 0.5f * (mse + cs);
        }
    }
}

extern "C" void kernel_launch(void* const* d_in, const int* in_sizes, int n_in,
                              void* d_out, int out_size) {
    const float* x = (const float*)d_in[0];
    const float* t = (const float*)d_in[1];
    float* out = (float*)d_out;
    int n = in_sizes[0];
    lamse_kernel<<<NBLK, NTHR>>>(x, t, out, n);
}